// round 1
// baseline (speedup 1.0000x reference)
#include <cuda_runtime.h>
#include <math.h>

#define B_ 4
#define S_ 2048
#define D_ 1024
#define H_ 16
#define HD_ 64
#define M_ (B_*S_)   // 8192

// Scratch (allocation-free rule: __device__ globals)
__device__ float g_q[(size_t)B_*H_*S_*HD_];
__device__ float g_k[(size_t)B_*H_*S_*HD_];
__device__ float g_v[(size_t)B_*H_*S_*HD_];
__device__ float g_wv[(size_t)B_*S_*D_];

// ---------------------------------------------------------------------------
// Fused QKV projection: out[b,h,s,e] = sum_d X[b,s,d]*W[h,d,e] + bias[h,e]
// 64x64 output tile per block, K-tile 16, 256 threads, 4x4 per thread.
// N-tile == one head (64 cols), so W slice loads are fully coalesced.
// blockIdx.z selects Q / K / V.
// ---------------------------------------------------------------------------
__global__ __launch_bounds__(256) void qkv_gemm(
    const float* __restrict__ X,
    const float* __restrict__ Wq, const float* __restrict__ bq,
    const float* __restrict__ Wk, const float* __restrict__ bk,
    const float* __restrict__ Wv, const float* __restrict__ bv)
{
    __shared__ __align__(16) float As[16][68];
    __shared__ __align__(16) float Bs[16][68];

    const int z = blockIdx.z;
    const float* __restrict__ W    = (z == 0) ? Wq : (z == 1) ? Wk : Wv;
    const float* __restrict__ bias = (z == 0) ? bq : (z == 1) ? bk : bv;
    float* __restrict__ out        = (z == 0) ? g_q : (z == 1) ? g_k : g_v;

    const int h   = blockIdx.x;        // head index == N tile
    const int m0  = blockIdx.y * 64;
    const int tid = threadIdx.x;
    const int tx  = tid & 15, ty = tid >> 4;
    const float* __restrict__ Wh = W + (size_t)h * D_ * HD_;

    float c[4][4] = {};

    for (int k0 = 0; k0 < D_; k0 += 16) {
        #pragma unroll
        for (int i = 0; i < 4; ++i) {
            int idx = tid + i * 256;
            int mm = idx >> 4, kk = idx & 15;
            As[kk][mm] = X[(size_t)(m0 + mm) * D_ + k0 + kk];
        }
        #pragma unroll
        for (int i = 0; i < 4; ++i) {
            int idx = tid + i * 256;
            int kk = idx >> 6, nn = idx & 63;
            Bs[kk][nn] = Wh[(size_t)(k0 + kk) * HD_ + nn];
        }
        __syncthreads();
        #pragma unroll
        for (int kk = 0; kk < 16; ++kk) {
            float4 a4 = *(const float4*)&As[kk][ty * 4];
            float4 b4 = *(const float4*)&Bs[kk][tx * 4];
            float a[4] = {a4.x, a4.y, a4.z, a4.w};
            float b[4] = {b4.x, b4.y, b4.z, b4.w};
            #pragma unroll
            for (int i = 0; i < 4; ++i)
                #pragma unroll
                for (int j = 0; j < 4; ++j)
                    c[i][j] = fmaf(a[i], b[j], c[i][j]);
        }
        __syncthreads();
    }

    #pragma unroll
    for (int i = 0; i < 4; ++i) {
        int m = m0 + ty * 4 + i;
        int b = m >> 11;        // / 2048
        int s = m & 2047;
        float* op = out + (((size_t)(b * H_ + h)) * S_ + s) * HD_ + tx * 4;
        #pragma unroll
        for (int j = 0; j < 4; ++j)
            op[j] = c[i][j] + bias[h * HD_ + tx * 4 + j];
    }
}

// ---------------------------------------------------------------------------
// Causal flash attention: one thread per query row, K/V tiles (64x64) in smem,
// per-key online softmax. q and o are register-resident (16 float4 each).
// ---------------------------------------------------------------------------
__global__ __launch_bounds__(128) void attn_kernel()
{
    __shared__ __align__(16) float Ks[64][64];
    __shared__ __align__(16) float Vs[64][64];

    const int bh  = blockIdx.y;            // b*H + h
    const int q0  = blockIdx.x * 128;
    const int tid = threadIdx.x;
    const int qi  = q0 + tid;

    const float* __restrict__ Qb = g_q + (size_t)bh * S_ * HD_;
    const float* __restrict__ Kb = g_k + (size_t)bh * S_ * HD_;
    const float* __restrict__ Vb = g_v + (size_t)bh * S_ * HD_;

    float4 q[16], o[16];
    const float4* qr = (const float4*)(Qb + (size_t)qi * HD_);
    #pragma unroll
    for (int d = 0; d < 16; ++d) { q[d] = qr[d]; o[d] = make_float4(0.f, 0.f, 0.f, 0.f); }

    float mrow = -INFINITY, l = 0.f;
    const int kend = q0 + 128;             // last key any row in this block can see

    for (int k0 = 0; k0 < kend; k0 += 64) {
        __syncthreads();                   // protect tiles from previous iter
        #pragma unroll
        for (int i = 0; i < 8; ++i) {
            int idx = tid + i * 128;
            int r = idx >> 4, c4 = idx & 15;
            ((float4*)&Ks[r][0])[c4] = ((const float4*)(Kb + (size_t)(k0 + r) * HD_))[c4];
            ((float4*)&Vs[r][0])[c4] = ((const float4*)(Vb + (size_t)(k0 + r) * HD_))[c4];
        }
        __syncthreads();

        const bool full = (k0 + 63 <= qi); // tile fully unmasked for this row

        for (int j = 0; j < 64; ++j) {
            const float4* kr = (const float4*)&Ks[j][0];
            float a0 = 0.f, a1 = 0.f, a2 = 0.f, a3 = 0.f;
            #pragma unroll
            for (int d = 0; d < 16; d += 4) {
                float4 kA = kr[d], kB = kr[d + 1], kC = kr[d + 2], kD = kr[d + 3];
                a0 = fmaf(q[d].x,     kA.x, fmaf(q[d].y,     kA.y, fmaf(q[d].z,     kA.z, fmaf(q[d].w,     kA.w, a0))));
                a1 = fmaf(q[d + 1].x, kB.x, fmaf(q[d + 1].y, kB.y, fmaf(q[d + 1].z, kB.z, fmaf(q[d + 1].w, kB.w, a1))));
                a2 = fmaf(q[d + 2].x, kC.x, fmaf(q[d + 2].y, kC.y, fmaf(q[d + 2].z, kC.z, fmaf(q[d + 2].w, kC.w, a2))));
                a3 = fmaf(q[d + 3].x, kD.x, fmaf(q[d + 3].y, kD.y, fmaf(q[d + 3].z, kD.z, fmaf(q[d + 3].w, kD.w, a3))));
            }
            float sv = ((a0 + a1) + (a2 + a3)) * 0.125f;   // 1/sqrt(64)
            if (!full && (k0 + j > qi)) sv = -INFINITY;

            float mnew = fmaxf(mrow, sv);
            if (mnew > mrow) {             // rare: new running max
                float corr = __expf(mrow - mnew);
                l *= corr;
                #pragma unroll
                for (int d = 0; d < 16; ++d) {
                    o[d].x *= corr; o[d].y *= corr; o[d].z *= corr; o[d].w *= corr;
                }
                mrow = mnew;
            }
            float p = __expf(sv - mrow);   // masked key -> exp(-inf) = 0
            l += p;

            const float4* vr = (const float4*)&Vs[j][0];
            #pragma unroll
            for (int d = 0; d < 16; ++d) {
                float4 vv = vr[d];
                o[d].x = fmaf(p, vv.x, o[d].x);
                o[d].y = fmaf(p, vv.y, o[d].y);
                o[d].z = fmaf(p, vv.z, o[d].z);
                o[d].w = fmaf(p, vv.w, o[d].w);
            }
        }
    }

    const float inv = 1.f / l;
    const int b = bh >> 4, h = bh & 15;
    float4* op = (float4*)(g_wv + ((size_t)(b * S_) + qi) * D_ + h * HD_);
    #pragma unroll
    for (int d = 0; d < 16; ++d) {
        float4 t = o[d];
        t.x *= inv; t.y *= inv; t.z *= inv; t.w *= inv;
        op[d] = t;
    }
}

// ---------------------------------------------------------------------------
// Output projection: out[m,n] = sum_k wv[m,k] * Wo[n,k] + bo[n]
// ---------------------------------------------------------------------------
__global__ __launch_bounds__(256) void out_gemm(
    const float* __restrict__ Wo, const float* __restrict__ bo,
    float* __restrict__ out)
{
    __shared__ __align__(16) float As[16][68];
    __shared__ __align__(16) float Bs[16][68];

    const int n0  = blockIdx.x * 64;
    const int m0  = blockIdx.y * 64;
    const int tid = threadIdx.x;
    const int tx  = tid & 15, ty = tid >> 4;

    float c[4][4] = {};

    for (int k0 = 0; k0 < D_; k0 += 16) {
        #pragma unroll
        for (int i = 0; i < 4; ++i) {
            int idx = tid + i * 256;
            int mm = idx >> 4, kk = idx & 15;
            As[kk][mm] = g_wv[(size_t)(m0 + mm) * D_ + k0 + kk];
        }
        #pragma unroll
        for (int i = 0; i < 4; ++i) {
            int idx = tid + i * 256;
            int nn = idx >> 4, kk = idx & 15;          // coalesced over k
            Bs[kk][nn] = Wo[(size_t)(n0 + nn) * D_ + k0 + kk];
        }
        __syncthreads();
        #pragma unroll
        for (int kk = 0; kk < 16; ++kk) {
            float4 a4 = *(const float4*)&As[kk][ty * 4];
            float4 b4 = *(const float4*)&Bs[kk][tx * 4];
            float a[4] = {a4.x, a4.y, a4.z, a4.w};
            float b[4] = {b4.x, b4.y, b4.z, b4.w};
            #pragma unroll
            for (int i = 0; i < 4; ++i)
                #pragma unroll
                for (int j = 0; j < 4; ++j)
                    c[i][j] = fmaf(a[i], b[j], c[i][j]);
        }
        __syncthreads();
    }

    #pragma unroll
    for (int i = 0; i < 4; ++i) {
        int m = m0 + ty * 4 + i;
        float* op = out + (size_t)m * D_ + n0 + tx * 4;
        #pragma unroll
        for (int j = 0; j < 4; ++j)
            op[j] = c[i][j] + bo[n0 + tx * 4 + j];
    }
}

extern "C" void kernel_launch(void* const* d_in, const int* in_sizes, int n_in,
                              void* d_out, int out_size)
{
    const float* X  = (const float*)d_in[0];
    const float* Wq = (const float*)d_in[1];
    const float* bq = (const float*)d_in[2];
    const float* Wk = (const float*)d_in[3];
    const float* bk = (const float*)d_in[4];
    const float* Wv = (const float*)d_in[5];
    const float* bv = (const float*)d_in[6];
    const float* Wo = (const float*)d_in[7];
    const float* bo = (const float*)d_in[8];
    float* out = (float*)d_out;

    qkv_gemm<<<dim3(H_, M_ / 64, 3), 256>>>(X, Wq, bq, Wk, bk, Wv, bv);
    attn_kernel<<<dim3(S_ / 128, B_ * H_), 128>>>();
    out_gemm<<<dim3(D_ / 64, M_ / 64), 256>>>(Wo, bo, out);
}

// round 4
// speedup vs baseline: 1.7919x; 1.7919x over previous
#include <cuda_runtime.h>
#include <cuda_fp16.h>
#include <math.h>
#include <stdint.h>

#define B_ 4
#define S_ 2048
#define D_ 1024
#define H_ 16
#define HD_ 64
#define M_ (B_*S_)   // 8192

// fp32 scratch
__device__ float g_q[(size_t)B_*H_*S_*HD_];
__device__ float g_k[(size_t)B_*H_*S_*HD_];
__device__ float g_v[(size_t)B_*H_*S_*HD_];
__device__ float g_wv[(size_t)B_*S_*D_];
// fp16 scratch
__device__ __half g_xh[(size_t)M_*D_];          // X fp16 [8192][1024]
__device__ __half g_wvh[(size_t)M_*D_];         // attention output fp16
__device__ __half g_wt[(size_t)3*H_*HD_*D_];    // QKV weights transposed [z][h][n=64][k=1024]
__device__ __half g_woh[(size_t)D_*D_];         // Wo fp16 [n][k]

// ---------------------------------------------------------------------------
// helpers
// ---------------------------------------------------------------------------
__device__ __forceinline__ uint32_t smem_u32(const void* p) {
    uint32_t a;
    asm("{ .reg .u64 t; cvta.to.shared.u64 t, %1; cvt.u32.u64 %0, t; }" : "=r"(a) : "l"(p));
    return a;
}
__device__ __forceinline__ void cpa16(uint32_t dst, const void* src) {
    asm volatile("cp.async.cg.shared.global [%0], [%1], 16;" :: "r"(dst), "l"(src));
}
__device__ __forceinline__ void cpa_commit() {
    asm volatile("cp.async.commit_group;" ::: "memory");
}

// smem tile geometry: 128 rows x 32 halves, row stride 80 bytes (5 x 16B -> conflict-free)
#define RS 80
#define TILE_BYTES (128 * RS)      // 10240
#define BUF_BYTES (2 * TILE_BYTES) // A+B per buffer
#define NKT 32                     // 1024 / 32

// load one 128x32-half tile pair (A,B) for k-chunk kt
__device__ __forceinline__ void load_tiles(uint32_t sA, uint32_t sB,
                                           const __half* __restrict__ A,
                                           const __half* __restrict__ Bg,
                                           int kt, int tid) {
    #pragma unroll
    for (int i = 0; i < 2; ++i) {
        int idx = tid + i * 256;
        int row = idx >> 2, c16 = idx & 3;
        const size_t go = (size_t)row * D_ + kt * 32 + c16 * 8;
        cpa16(sA + row * RS + c16 * 16, A + go);
        cpa16(sB + row * RS + c16 * 16, Bg + go);
    }
}

// one BK=32 compute step for this warp
__device__ __forceinline__ void warp_compute(uint32_t sA, uint32_t sB,
                                             int warp_m, int warp_n, int lane,
                                             float c[4][4][4]) {
    #pragma unroll
    for (int ks = 0; ks < 2; ++ks) {
        uint32_t a[4][4];
        #pragma unroll
        for (int i = 0; i < 4; ++i) {
            int row = warp_m * 64 + i * 16 + (lane & 15);
            uint32_t addr = sA + row * RS + (ks * 16 + (lane >> 4) * 8) * 2;
            asm volatile("ldmatrix.sync.aligned.m8n8.x4.shared.b16 {%0,%1,%2,%3}, [%4];"
                         : "=r"(a[i][0]), "=r"(a[i][1]), "=r"(a[i][2]), "=r"(a[i][3])
                         : "r"(addr));
        }
        uint32_t b[4][2];
        #pragma unroll
        for (int jj = 0; jj < 2; ++jj) {
            int g = lane >> 3, lr = lane & 7;
            int n = warp_n * 32 + jj * 16 + (g >> 1) * 8 + lr;
            uint32_t addr = sB + n * RS + (ks * 16 + (g & 1) * 8) * 2;
            uint32_t r0, r1, r2, r3;
            asm volatile("ldmatrix.sync.aligned.m8n8.x4.shared.b16 {%0,%1,%2,%3}, [%4];"
                         : "=r"(r0), "=r"(r1), "=r"(r2), "=r"(r3) : "r"(addr));
            b[jj * 2][0] = r0; b[jj * 2][1] = r1;
            b[jj * 2 + 1][0] = r2; b[jj * 2 + 1][1] = r3;
        }
        #pragma unroll
        for (int i = 0; i < 4; ++i)
            #pragma unroll
            for (int j = 0; j < 4; ++j)
                asm volatile("mma.sync.aligned.m16n8k16.row.col.f32.f16.f16.f32 "
                             "{%0,%1,%2,%3}, {%4,%5,%6,%7}, {%8,%9}, {%0,%1,%2,%3};"
                             : "+f"(c[i][j][0]), "+f"(c[i][j][1]),
                               "+f"(c[i][j][2]), "+f"(c[i][j][3])
                             : "r"(a[i][0]), "r"(a[i][1]), "r"(a[i][2]), "r"(a[i][3]),
                               "r"(b[j][0]), "r"(b[j][1]));
    }
}

// full mainloop: C[128x128] = A[128x1024] * B[128x1024]^T (both K-major)
__device__ __forceinline__ void gemm_main(uint32_t s, const __half* __restrict__ A,
                                          const __half* __restrict__ Bg,
                                          int tid, int warp_m, int warp_n, int lane,
                                          float c[4][4][4]) {
    load_tiles(s, s + TILE_BYTES, A, Bg, 0, tid); cpa_commit();
    load_tiles(s + BUF_BYTES, s + BUF_BYTES + TILE_BYTES, A, Bg, 1, tid); cpa_commit();

    for (int kt = 0; kt < NKT; ++kt) {
        const uint32_t boff = (kt & 1) * BUF_BYTES;
        if (kt < NKT - 1) asm volatile("cp.async.wait_group 1;" ::: "memory");
        else              asm volatile("cp.async.wait_group 0;" ::: "memory");
        __syncthreads();
        warp_compute(s + boff, s + boff + TILE_BYTES, warp_m, warp_n, lane, c);
        __syncthreads();
        if (kt + 2 < NKT) {
            load_tiles(s + boff, s + boff + TILE_BYTES, A, Bg, kt + 2, tid);
            cpa_commit();
        }
    }
}

// ---------------------------------------------------------------------------
// QKV projection: per block 128 rows x 2 heads (N=128)
// ---------------------------------------------------------------------------
__global__ __launch_bounds__(256) void qkv_mma(
    const __half* __restrict__ Xh, const __half* __restrict__ Wt,
    const float* __restrict__ bq, const float* __restrict__ bk,
    const float* __restrict__ bv) {
    __shared__ __align__(16) char sm[2 * BUF_BYTES];
    const uint32_t s = smem_u32(sm);
    const int tid = threadIdx.x, lane = tid & 31, wid = tid >> 5;
    const int warp_m = wid & 1, warp_n = wid >> 1;
    const int z = blockIdx.z, h0 = blockIdx.x * 2, m0 = blockIdx.y * 128;

    const __half* A  = Xh + (size_t)m0 * D_;
    const __half* Bg = Wt + ((size_t)(z * H_ + h0) * HD_) * D_;
    const float* bias = (z == 0) ? bq : (z == 1) ? bk : bv;
    float* out        = (z == 0) ? g_q : (z == 1) ? g_k : g_v;

    float c[4][4][4] = {};
    gemm_main(s, A, Bg, tid, warp_m, warp_n, lane, c);

    #pragma unroll
    for (int i = 0; i < 4; ++i) {
        #pragma unroll
        for (int j = 0; j < 4; ++j) {
            const int n = warp_n * 32 + j * 8 + (lane & 3) * 2;
            const int head = h0 + (n >> 6), e = n & 63;
            const float b0 = bias[head * HD_ + e], b1 = bias[head * HD_ + e + 1];
            #pragma unroll
            for (int half_ = 0; half_ < 2; ++half_) {
                const int m = m0 + warp_m * 64 + i * 16 + (lane >> 2) + half_ * 8;
                const int bb = m >> 11, sI = m & 2047;
                float2 v;
                v.x = c[i][j][half_ * 2 + 0] + b0;
                v.y = c[i][j][half_ * 2 + 1] + b1;
                *(float2*)(out + (((size_t)(bb * H_ + head) * S_ + sI) * HD_ + e)) = v;
            }
        }
    }
}

// ---------------------------------------------------------------------------
// Output projection: C[8192x1024] = WVh * Woh^T + bo
// ---------------------------------------------------------------------------
__global__ __launch_bounds__(256) void out_mma(
    const __half* __restrict__ WVh, const __half* __restrict__ Woh,
    const float* __restrict__ bo, float* __restrict__ outp) {
    __shared__ __align__(16) char sm[2 * BUF_BYTES];
    const uint32_t s = smem_u32(sm);
    const int tid = threadIdx.x, lane = tid & 31, wid = tid >> 5;
    const int warp_m = wid & 1, warp_n = wid >> 1;
    const int n0 = blockIdx.x * 128, m0 = blockIdx.y * 128;

    const __half* A  = WVh + (size_t)m0 * D_;
    const __half* Bg = Woh + (size_t)n0 * D_;

    float c[4][4][4] = {};
    gemm_main(s, A, Bg, tid, warp_m, warp_n, lane, c);

    #pragma unroll
    for (int i = 0; i < 4; ++i) {
        #pragma unroll
        for (int j = 0; j < 4; ++j) {
            const int n = n0 + warp_n * 32 + j * 8 + (lane & 3) * 2;
            const float b0 = bo[n], b1 = bo[n + 1];
            #pragma unroll
            for (int half_ = 0; half_ < 2; ++half_) {
                const int m = m0 + warp_m * 64 + i * 16 + (lane >> 2) + half_ * 8;
                float2 v;
                v.x = c[i][j][half_ * 2 + 0] + b0;
                v.y = c[i][j][half_ * 2 + 1] + b1;
                *(float2*)(outp + (size_t)m * D_ + n) = v;
            }
        }
    }
}

// ---------------------------------------------------------------------------
// converts + weight transpose
// ---------------------------------------------------------------------------
__global__ void cvt_f32_f16(const float* __restrict__ in, __half* __restrict__ out, int n) {
    int i = (blockIdx.x * blockDim.x + threadIdx.x) * 4;
    if (i < n) {
        float4 v = *(const float4*)(in + i);
        __half2* o = (__half2*)(out + i);
        o[0] = __floats2half2_rn(v.x, v.y);
        o[1] = __floats2half2_rn(v.z, v.w);
    }
}

// W[h][k=1024][n=64] (per z) -> g_wt[z][h][n][k] fp16
__global__ void wtrans(const float* __restrict__ Wq, const float* __restrict__ Wk,
                       const float* __restrict__ Wv) {
    __shared__ float t[32][33];
    const int zh = blockIdx.z, z = zh >> 4, h = zh & 15;
    const float* W = ((z == 0) ? Wq : (z == 1) ? Wk : Wv) + (size_t)h * D_ * HD_;
    __half* out = g_wt + (size_t)zh * HD_ * D_;
    const int n0 = blockIdx.x * 32, k0 = blockIdx.y * 32;
    const int tx = threadIdx.x, ty = threadIdx.y;   // 32 x 8
    #pragma unroll
    for (int i = 0; i < 32; i += 8)
        t[ty + i][tx] = W[(size_t)(k0 + ty + i) * HD_ + n0 + tx];
    __syncthreads();
    #pragma unroll
    for (int i = 0; i < 32; i += 8)
        out[(size_t)(n0 + ty + i) * D_ + k0 + tx] = __float2half_rn(t[tx][ty + i]);
}

// ---------------------------------------------------------------------------
// fp32 causal flash attention (known correct)
// ---------------------------------------------------------------------------
__global__ __launch_bounds__(128) void attn_kernel() {
    __shared__ __align__(16) float Ks[64][64];
    __shared__ __align__(16) float Vs[64][64];

    const int bh = blockIdx.y;
    const int q0 = blockIdx.x * 128;
    const int tid = threadIdx.x;
    const int qi = q0 + tid;

    const float* __restrict__ Qb = g_q + (size_t)bh * S_ * HD_;
    const float* __restrict__ Kb = g_k + (size_t)bh * S_ * HD_;
    const float* __restrict__ Vb = g_v + (size_t)bh * S_ * HD_;

    float4 q[16], o[16];
    const float4* qr = (const float4*)(Qb + (size_t)qi * HD_);
    #pragma unroll
    for (int d = 0; d < 16; ++d) { q[d] = qr[d]; o[d] = make_float4(0.f, 0.f, 0.f, 0.f); }

    float mrow = -INFINITY, l = 0.f;
    const int kend = q0 + 128;

    for (int k0 = 0; k0 < kend; k0 += 64) {
        __syncthreads();
        #pragma unroll
        for (int i = 0; i < 8; ++i) {
            int idx = tid + i * 128;
            int r = idx >> 4, c4 = idx & 15;
            ((float4*)&Ks[r][0])[c4] = ((const float4*)(Kb + (size_t)(k0 + r) * HD_))[c4];
            ((float4*)&Vs[r][0])[c4] = ((const float4*)(Vb + (size_t)(k0 + r) * HD_))[c4];
        }
        __syncthreads();

        const bool full = (k0 + 63 <= qi);

        for (int j = 0; j < 64; ++j) {
            const float4* kr = (const float4*)&Ks[j][0];
            float a0 = 0.f, a1 = 0.f, a2 = 0.f, a3 = 0.f;
            #pragma unroll
            for (int d = 0; d < 16; d += 4) {
                float4 kA = kr[d], kB = kr[d + 1], kC = kr[d + 2], kD = kr[d + 3];
                a0 = fmaf(q[d].x,     kA.x, fmaf(q[d].y,     kA.y, fmaf(q[d].z,     kA.z, fmaf(q[d].w,     kA.w, a0))));
                a1 = fmaf(q[d + 1].x, kB.x, fmaf(q[d + 1].y, kB.y, fmaf(q[d + 1].z, kB.z, fmaf(q[d + 1].w, kB.w, a1))));
                a2 = fmaf(q[d + 2].x, kC.x, fmaf(q[d + 2].y, kC.y, fmaf(q[d + 2].z, kC.z, fmaf(q[d + 2].w, kC.w, a2))));
                a3 = fmaf(q[d + 3].x, kD.x, fmaf(q[d + 3].y, kD.y, fmaf(q[d + 3].z, kD.z, fmaf(q[d + 3].w, kD.w, a3))));
            }
            float sv = ((a0 + a1) + (a2 + a3)) * 0.125f;
            if (!full && (k0 + j > qi)) sv = -INFINITY;

            float mnew = fmaxf(mrow, sv);
            if (mnew > mrow) {
                float corr = __expf(mrow - mnew);
                l *= corr;
                #pragma unroll
                for (int d = 0; d < 16; ++d) {
                    o[d].x *= corr; o[d].y *= corr; o[d].z *= corr; o[d].w *= corr;
                }
                mrow = mnew;
            }
            float p = __expf(sv - mrow);
            l += p;

            const float4* vr = (const float4*)&Vs[j][0];
            #pragma unroll
            for (int d = 0; d < 16; ++d) {
                float4 vv = vr[d];
                o[d].x = fmaf(p, vv.x, o[d].x);
                o[d].y = fmaf(p, vv.y, o[d].y);
                o[d].z = fmaf(p, vv.z, o[d].z);
                o[d].w = fmaf(p, vv.w, o[d].w);
            }
        }
    }

    const float inv = 1.f / l;
    const int b = bh >> 4, h = bh & 15;
    float4* op = (float4*)(g_wv + ((size_t)(b * S_) + qi) * D_ + h * HD_);
    #pragma unroll
    for (int d = 0; d < 16; ++d) {
        float4 t = o[d];
        t.x *= inv; t.y *= inv; t.z *= inv; t.w *= inv;
        op[d] = t;
    }
}

// ---------------------------------------------------------------------------
extern "C" void kernel_launch(void* const* d_in, const int* in_sizes, int n_in,
                              void* d_out, int out_size) {
    const float* X  = (const float*)d_in[0];
    const float* Wq = (const float*)d_in[1];
    const float* bq = (const float*)d_in[2];
    const float* Wk = (const float*)d_in[3];
    const float* bk = (const float*)d_in[4];
    const float* Wv = (const float*)d_in[5];
    const float* bv = (const float*)d_in[6];
    const float* Wo = (const float*)d_in[7];
    const float* bo = (const float*)d_in[8];
    float* out = (float*)d_out;

    __half* xh  = nullptr; cudaGetSymbolAddress((void**)&xh,  g_xh);
    __half* wvh = nullptr; cudaGetSymbolAddress((void**)&wvh, g_wvh);
    __half* wt  = nullptr; cudaGetSymbolAddress((void**)&wt,  g_wt);
    __half* woh = nullptr; cudaGetSymbolAddress((void**)&woh, g_woh);
    float*  wv  = nullptr; cudaGetSymbolAddress((void**)&wv,  g_wv);

    cvt_f32_f16<<<(M_ * D_) / 1024, 256>>>(X, xh, M_ * D_);
    cvt_f32_f16<<<(D_ * D_) / 1024, 256>>>(Wo, woh, D_ * D_);
    wtrans<<<dim3(2, 32, 48), dim3(32, 8)>>>(Wq, Wk, Wv);

    qkv_mma<<<dim3(H_ / 2, M_ / 128, 3), 256>>>(xh, wt, bq, bk, bv);
    attn_kernel<<<dim3(S_ / 128, B_ * H_), 128>>>();
    cvt_f32_f16<<<(M_ * D_) / 1024, 256>>>(wv, wvh, M_ * D_);
    out_mma<<<dim3(D_ / 128, M_ / 128), 256>>>(wvh, woh, bo, out);
}

// round 5
// speedup vs baseline: 7.8518x; 4.3819x over previous
#include <cuda_runtime.h>
#include <cuda_fp16.h>
#include <math.h>
#include <stdint.h>

#define B_ 4
#define S_ 2048
#define D_ 1024
#define H_ 16
#define HD_ 64
#define M_ (B_*S_)   // 8192

// fp16 scratch
__device__ __half g_qh[(size_t)B_*H_*S_*HD_];   // Q fp16 [bh][s][64]
__device__ __half g_kh[(size_t)B_*H_*S_*HD_];
__device__ __half g_vh[(size_t)B_*H_*S_*HD_];
__device__ __half g_xh[(size_t)M_*D_];          // X fp16
__device__ __half g_wvh[(size_t)M_*D_];         // attention output fp16 [b][s][D]
__device__ __half g_wt[(size_t)3*H_*HD_*D_];    // QKV weights [z][h][n=64][k=1024]
__device__ __half g_woh[(size_t)D_*D_];         // Wo fp16 [n][k]

// ---------------------------------------------------------------------------
// helpers
// ---------------------------------------------------------------------------
__device__ __forceinline__ uint32_t smem_u32(const void* p) {
    uint32_t a;
    asm("{ .reg .u64 t; cvta.to.shared.u64 t, %1; cvt.u32.u64 %0, t; }" : "=r"(a) : "l"(p));
    return a;
}
__device__ __forceinline__ void cpa16(uint32_t dst, const void* src) {
    asm volatile("cp.async.cg.shared.global [%0], [%1], 16;" :: "r"(dst), "l"(src));
}
__device__ __forceinline__ void cpa_commit() {
    asm volatile("cp.async.commit_group;" ::: "memory");
}
__device__ __forceinline__ float ex2(float x) {
    float r; asm("ex2.approx.ftz.f32 %0, %1;" : "=f"(r) : "f"(x)); return r;
}
__device__ __forceinline__ void mma16816(float c[4], const uint32_t a[4], const uint32_t b[2]) {
    asm volatile("mma.sync.aligned.m16n8k16.row.col.f32.f16.f16.f32 "
                 "{%0,%1,%2,%3}, {%4,%5,%6,%7}, {%8,%9}, {%0,%1,%2,%3};"
                 : "+f"(c[0]), "+f"(c[1]), "+f"(c[2]), "+f"(c[3])
                 : "r"(a[0]), "r"(a[1]), "r"(a[2]), "r"(a[3]), "r"(b[0]), "r"(b[1]));
}

// ======================= GEMM machinery (validated R4) ======================
#define RS 80
#define TILE_BYTES (128 * RS)
#define BUF_BYTES (2 * TILE_BYTES)
#define NKT 32

__device__ __forceinline__ void load_tiles(uint32_t sA, uint32_t sB,
                                           const __half* __restrict__ A,
                                           const __half* __restrict__ Bg,
                                           int kt, int tid) {
    #pragma unroll
    for (int i = 0; i < 2; ++i) {
        int idx = tid + i * 256;
        int row = idx >> 2, c16 = idx & 3;
        const size_t go = (size_t)row * D_ + kt * 32 + c16 * 8;
        cpa16(sA + row * RS + c16 * 16, A + go);
        cpa16(sB + row * RS + c16 * 16, Bg + go);
    }
}

__device__ __forceinline__ void warp_compute(uint32_t sA, uint32_t sB,
                                             int warp_m, int warp_n, int lane,
                                             float c[4][4][4]) {
    #pragma unroll
    for (int ks = 0; ks < 2; ++ks) {
        uint32_t a[4][4];
        #pragma unroll
        for (int i = 0; i < 4; ++i) {
            int row = warp_m * 64 + i * 16 + (lane & 15);
            uint32_t addr = sA + row * RS + (ks * 16 + (lane >> 4) * 8) * 2;
            asm volatile("ldmatrix.sync.aligned.m8n8.x4.shared.b16 {%0,%1,%2,%3}, [%4];"
                         : "=r"(a[i][0]), "=r"(a[i][1]), "=r"(a[i][2]), "=r"(a[i][3])
                         : "r"(addr));
        }
        uint32_t b[4][2];
        #pragma unroll
        for (int jj = 0; jj < 2; ++jj) {
            int g = lane >> 3, lr = lane & 7;
            int n = warp_n * 32 + jj * 16 + (g >> 1) * 8 + lr;
            uint32_t addr = sB + n * RS + (ks * 16 + (g & 1) * 8) * 2;
            uint32_t r0, r1, r2, r3;
            asm volatile("ldmatrix.sync.aligned.m8n8.x4.shared.b16 {%0,%1,%2,%3}, [%4];"
                         : "=r"(r0), "=r"(r1), "=r"(r2), "=r"(r3) : "r"(addr));
            b[jj * 2][0] = r0; b[jj * 2][1] = r1;
            b[jj * 2 + 1][0] = r2; b[jj * 2 + 1][1] = r3;
        }
        #pragma unroll
        for (int i = 0; i < 4; ++i)
            #pragma unroll
            for (int j = 0; j < 4; ++j)
                mma16816(c[i][j], a[i], b[j]);
    }
}

__device__ __forceinline__ void gemm_main(uint32_t s, const __half* __restrict__ A,
                                          const __half* __restrict__ Bg,
                                          int tid, int warp_m, int warp_n, int lane,
                                          float c[4][4][4]) {
    load_tiles(s, s + TILE_BYTES, A, Bg, 0, tid); cpa_commit();
    load_tiles(s + BUF_BYTES, s + BUF_BYTES + TILE_BYTES, A, Bg, 1, tid); cpa_commit();

    for (int kt = 0; kt < NKT; ++kt) {
        const uint32_t boff = (kt & 1) * BUF_BYTES;
        if (kt < NKT - 1) asm volatile("cp.async.wait_group 1;" ::: "memory");
        else              asm volatile("cp.async.wait_group 0;" ::: "memory");
        __syncthreads();
        warp_compute(s + boff, s + boff + TILE_BYTES, warp_m, warp_n, lane, c);
        __syncthreads();
        if (kt + 2 < NKT) {
            load_tiles(s + boff, s + boff + TILE_BYTES, A, Bg, kt + 2, tid);
            cpa_commit();
        }
    }
}

// ---------------------------------------------------------------------------
// QKV projection -> fp16 Q/K/V
// ---------------------------------------------------------------------------
__global__ __launch_bounds__(256) void qkv_mma(
    const __half* __restrict__ Xh, const __half* __restrict__ Wt,
    const float* __restrict__ bq, const float* __restrict__ bk,
    const float* __restrict__ bv) {
    __shared__ __align__(16) char sm[2 * BUF_BYTES];
    const uint32_t s = smem_u32(sm);
    const int tid = threadIdx.x, lane = tid & 31, wid = tid >> 5;
    const int warp_m = wid & 1, warp_n = wid >> 1;
    const int z = blockIdx.z, h0 = blockIdx.x * 2, m0 = blockIdx.y * 128;

    const __half* A  = Xh + (size_t)m0 * D_;
    const __half* Bg = Wt + ((size_t)(z * H_ + h0) * HD_) * D_;
    const float* bias = (z == 0) ? bq : (z == 1) ? bk : bv;
    __half* out       = (z == 0) ? g_qh : (z == 1) ? g_kh : g_vh;

    float c[4][4][4] = {};
    gemm_main(s, A, Bg, tid, warp_m, warp_n, lane, c);

    #pragma unroll
    for (int i = 0; i < 4; ++i) {
        #pragma unroll
        for (int j = 0; j < 4; ++j) {
            const int n = warp_n * 32 + j * 8 + (lane & 3) * 2;
            const int head = h0 + (n >> 6), e = n & 63;
            const float b0 = bias[head * HD_ + e], b1 = bias[head * HD_ + e + 1];
            #pragma unroll
            for (int half_ = 0; half_ < 2; ++half_) {
                const int m = m0 + warp_m * 64 + i * 16 + (lane >> 2) + half_ * 8;
                const int bb = m >> 11, sI = m & 2047;
                __half2 hv = __floats2half2_rn(c[i][j][half_ * 2 + 0] + b0,
                                               c[i][j][half_ * 2 + 1] + b1);
                *(__half2*)(out + (((size_t)(bb * H_ + head) * S_ + sI) * HD_ + e)) = hv;
            }
        }
    }
}

// ---------------------------------------------------------------------------
// Output projection: C[8192x1024] = WVh * Woh^T + bo
// ---------------------------------------------------------------------------
__global__ __launch_bounds__(256) void out_mma(
    const __half* __restrict__ WVh, const __half* __restrict__ Woh,
    const float* __restrict__ bo, float* __restrict__ outp) {
    __shared__ __align__(16) char sm[2 * BUF_BYTES];
    const uint32_t s = smem_u32(sm);
    const int tid = threadIdx.x, lane = tid & 31, wid = tid >> 5;
    const int warp_m = wid & 1, warp_n = wid >> 1;
    const int n0 = blockIdx.x * 128, m0 = blockIdx.y * 128;

    const __half* A  = WVh + (size_t)m0 * D_;
    const __half* Bg = Woh + (size_t)n0 * D_;

    float c[4][4][4] = {};
    gemm_main(s, A, Bg, tid, warp_m, warp_n, lane, c);

    #pragma unroll
    for (int i = 0; i < 4; ++i) {
        #pragma unroll
        for (int j = 0; j < 4; ++j) {
            const int n = n0 + warp_n * 32 + j * 8 + (lane & 3) * 2;
            const float b0 = bo[n], b1 = bo[n + 1];
            #pragma unroll
            for (int half_ = 0; half_ < 2; ++half_) {
                const int m = m0 + warp_m * 64 + i * 16 + (lane >> 2) + half_ * 8;
                float2 v;
                v.x = c[i][j][half_ * 2 + 0] + b0;
                v.y = c[i][j][half_ * 2 + 1] + b1;
                *(float2*)(outp + (size_t)m * D_ + n) = v;
            }
        }
    }
}

// ======================= tensor-core flash attention ========================
// 256 threads / 8 warps; warp w owns q-rows [q0+16w, q0+16w+16).
// K,V tiles 64 keys x 64 hd fp16 in smem (144B row stride), double-buffered.
#define ARS 144
#define ATILE (64 * ARS)           // 9216 B

__global__ __launch_bounds__(256) void attn_mma() {
    __shared__ __align__(16) char sm[2 * 2 * ATILE];   // 36864 B
    const uint32_t s = smem_u32(sm);
    const int tid = threadIdx.x, lane = tid & 31, w = tid >> 5;
    const int bh = blockIdx.y, q0 = blockIdx.x * 128;

    const __half* __restrict__ Qb = g_qh + (size_t)bh * S_ * HD_;
    const __half* __restrict__ Kb = g_kh + (size_t)bh * S_ * HD_;
    const __half* __restrict__ Vb = g_vh + (size_t)bh * S_ * HD_;

    // Q fragments: a[t] covers hd 16t..16t+15 for rows r, r+8
    const int r0 = q0 + w * 16 + (lane >> 2);
    const int cq = lane & 3;
    uint32_t qf[4][4];
    {
        const __half2* Qr0 = (const __half2*)(Qb + (size_t)r0 * HD_);
        const __half2* Qr1 = (const __half2*)(Qb + (size_t)(r0 + 8) * HD_);
        #pragma unroll
        for (int t = 0; t < 4; ++t) {
            qf[t][0] = *(const uint32_t*)&Qr0[t * 8 + cq];
            qf[t][1] = *(const uint32_t*)&Qr1[t * 8 + cq];
            qf[t][2] = *(const uint32_t*)&Qr0[t * 8 + 4 + cq];
            qf[t][3] = *(const uint32_t*)&Qr1[t * 8 + 4 + cq];
        }
    }

    float o[8][4];
    #pragma unroll
    for (int j = 0; j < 8; ++j)
        #pragma unroll
        for (int x = 0; x < 4; ++x) o[j][x] = 0.f;
    float m0 = -INFINITY, m1 = -INFINITY, l0 = 0.f, l1 = 0.f;

    const int NT = (q0 + 128) / 64;
    const float SC = 0.18033688f;    // 0.125 * log2(e)

    // tile loader: K at buf base, V at +ATILE
    auto load_tile = [&](int kt, int buf) {
        const uint32_t base = s + buf * (2 * ATILE);
        #pragma unroll
        for (int i = 0; i < 2; ++i) {
            int idx = tid + i * 256;
            int row = idx >> 3, c = idx & 7;
            const size_t go = (size_t)(kt * 64 + row) * HD_ + c * 8;
            cpa16(base + row * ARS + c * 16, Kb + go);
            cpa16(base + ATILE + row * ARS + c * 16, Vb + go);
        }
    };

    load_tile(0, 0); cpa_commit();
    if (NT > 1) { load_tile(1, 1); cpa_commit(); }

    // per-lane ldmatrix base offsets
    const uint32_t kb_lane = (lane & 7) * ARS + ((lane >> 3) & 1) * 16;  // K: rows j*8.., hd +0/+8
    const uint32_t vb_lane = (lane & 15) * ARS;                           // V: rows 16t.., col j*16B

    for (int kt = 0; kt < NT; ++kt) {
        const int buf = kt & 1, k0 = kt * 64;
        const uint32_t sK = s + buf * (2 * ATILE), sV = sK + ATILE;
        if (kt < NT - 1) asm volatile("cp.async.wait_group 1;" ::: "memory");
        else             asm volatile("cp.async.wait_group 0;" ::: "memory");
        __syncthreads();

        // ---- S = Q K^T (scaled fp32) ----
        float sa[8][4];
        #pragma unroll
        for (int j = 0; j < 8; ++j)
            #pragma unroll
            for (int x = 0; x < 4; ++x) sa[j][x] = 0.f;
        #pragma unroll
        for (int t = 0; t < 4; ++t) {
            #pragma unroll
            for (int j = 0; j < 8; ++j) {
                uint32_t b[2];
                uint32_t addr = sK + kb_lane + j * 8 * ARS + t * 32;
                asm volatile("ldmatrix.sync.aligned.m8n8.x2.shared.b16 {%0,%1}, [%2];"
                             : "=r"(b[0]), "=r"(b[1]) : "r"(addr));
                mma16816(sa[j], qf[t], b);
            }
        }

        // ---- mask + online softmax ----
        const bool needmask = (k0 + 63 > r0);
        float tm0 = -INFINITY, tm1 = -INFINITY;
        #pragma unroll
        for (int j = 0; j < 8; ++j) {
            float v0 = sa[j][0] * SC, v1 = sa[j][1] * SC;
            float v2 = sa[j][2] * SC, v3 = sa[j][3] * SC;
            if (needmask) {
                const int col = k0 + j * 8 + (lane & 3) * 2;
                if (col > r0)         v0 = -INFINITY;
                if (col + 1 > r0)     v1 = -INFINITY;
                if (col > r0 + 8)     v2 = -INFINITY;
                if (col + 1 > r0 + 8) v3 = -INFINITY;
            }
            sa[j][0] = v0; sa[j][1] = v1; sa[j][2] = v2; sa[j][3] = v3;
            tm0 = fmaxf(tm0, fmaxf(v0, v1));
            tm1 = fmaxf(tm1, fmaxf(v2, v3));
        }
        tm0 = fmaxf(tm0, __shfl_xor_sync(0xffffffffu, tm0, 1));
        tm0 = fmaxf(tm0, __shfl_xor_sync(0xffffffffu, tm0, 2));
        tm1 = fmaxf(tm1, __shfl_xor_sync(0xffffffffu, tm1, 1));
        tm1 = fmaxf(tm1, __shfl_xor_sync(0xffffffffu, tm1, 2));

        const float mn0 = fmaxf(m0, tm0), mn1 = fmaxf(m1, tm1);
        const float c0 = ex2(m0 - mn0), c1 = ex2(m1 - mn1);
        m0 = mn0; m1 = mn1;

        float ts0 = 0.f, ts1 = 0.f;
        uint32_t pa[4][4];
        #pragma unroll
        for (int j = 0; j < 8; ++j) {
            const float p0 = ex2(sa[j][0] - mn0), p1 = ex2(sa[j][1] - mn0);
            const float p2 = ex2(sa[j][2] - mn1), p3 = ex2(sa[j][3] - mn1);
            ts0 += p0 + p1; ts1 += p2 + p3;
            const __half2 h01 = __floats2half2_rn(p0, p1);
            const __half2 h23 = __floats2half2_rn(p2, p3);
            const int t = j >> 1;
            if ((j & 1) == 0) {
                pa[t][0] = *(const uint32_t*)&h01;
                pa[t][1] = *(const uint32_t*)&h23;
            } else {
                pa[t][2] = *(const uint32_t*)&h01;
                pa[t][3] = *(const uint32_t*)&h23;
            }
        }
        ts0 += __shfl_xor_sync(0xffffffffu, ts0, 1);
        ts0 += __shfl_xor_sync(0xffffffffu, ts0, 2);
        ts1 += __shfl_xor_sync(0xffffffffu, ts1, 1);
        ts1 += __shfl_xor_sync(0xffffffffu, ts1, 2);
        l0 = l0 * c0 + ts0;
        l1 = l1 * c1 + ts1;

        #pragma unroll
        for (int j = 0; j < 8; ++j) {
            o[j][0] *= c0; o[j][1] *= c0;
            o[j][2] *= c1; o[j][3] *= c1;
        }

        // ---- O += P V ----
        #pragma unroll
        for (int t = 0; t < 4; ++t) {
            #pragma unroll
            for (int j = 0; j < 8; ++j) {
                uint32_t b[2];
                uint32_t addr = sV + vb_lane + t * 16 * ARS + j * 16;
                asm volatile("ldmatrix.sync.aligned.m8n8.x2.trans.shared.b16 {%0,%1}, [%2];"
                             : "=r"(b[0]), "=r"(b[1]) : "r"(addr));
                mma16816(o[j], pa[t], b);
            }
        }

        __syncthreads();
        if (kt + 2 < NT) { load_tile(kt + 2, buf); cpa_commit(); }
    }

    // ---- epilogue: normalize + write fp16 WV ----
    const float i0 = 1.f / l0, i1 = 1.f / l1;
    const int b = bh >> 4, h = bh & 15;
    __half* out0 = g_wvh + ((size_t)(b * S_) + r0) * D_ + h * HD_ + (lane & 3) * 2;
    __half* out1 = g_wvh + ((size_t)(b * S_) + r0 + 8) * D_ + h * HD_ + (lane & 3) * 2;
    #pragma unroll
    for (int j = 0; j < 8; ++j) {
        *(__half2*)(out0 + j * 8) = __floats2half2_rn(o[j][0] * i0, o[j][1] * i0);
        *(__half2*)(out1 + j * 8) = __floats2half2_rn(o[j][2] * i1, o[j][3] * i1);
    }
}

// ---------------------------------------------------------------------------
// converts + weight transpose
// ---------------------------------------------------------------------------
__global__ void cvt_f32_f16(const float* __restrict__ in, __half* __restrict__ out, int n) {
    int i = (blockIdx.x * blockDim.x + threadIdx.x) * 4;
    if (i < n) {
        float4 v = *(const float4*)(in + i);
        __half2* o = (__half2*)(out + i);
        o[0] = __floats2half2_rn(v.x, v.y);
        o[1] = __floats2half2_rn(v.z, v.w);
    }
}

__global__ void wtrans(const float* __restrict__ Wq, const float* __restrict__ Wk,
                       const float* __restrict__ Wv) {
    __shared__ float t[32][33];
    const int zh = blockIdx.z, z = zh >> 4, h = zh & 15;
    const float* W = ((z == 0) ? Wq : (z == 1) ? Wk : Wv) + (size_t)h * D_ * HD_;
    __half* out = g_wt + (size_t)zh * HD_ * D_;
    const int n0 = blockIdx.x * 32, k0 = blockIdx.y * 32;
    const int tx = threadIdx.x, ty = threadIdx.y;
    #pragma unroll
    for (int i = 0; i < 32; i += 8)
        t[ty + i][tx] = W[(size_t)(k0 + ty + i) * HD_ + n0 + tx];
    __syncthreads();
    #pragma unroll
    for (int i = 0; i < 32; i += 8)
        out[(size_t)(n0 + ty + i) * D_ + k0 + tx] = __float2half_rn(t[tx][ty + i]);
}

// ---------------------------------------------------------------------------
extern "C" void kernel_launch(void* const* d_in, const int* in_sizes, int n_in,
                              void* d_out, int out_size) {
    const float* X  = (const float*)d_in[0];
    const float* Wq = (const float*)d_in[1];
    const float* bq = (const float*)d_in[2];
    const float* Wk = (const float*)d_in[3];
    const float* bk = (const float*)d_in[4];
    const float* Wv = (const float*)d_in[5];
    const float* bv = (const float*)d_in[6];
    const float* Wo = (const float*)d_in[7];
    const float* bo = (const float*)d_in[8];
    float* out = (float*)d_out;

    __half* xh  = nullptr; cudaGetSymbolAddress((void**)&xh,  g_xh);
    __half* wvh = nullptr; cudaGetSymbolAddress((void**)&wvh, g_wvh);
    __half* wt  = nullptr; cudaGetSymbolAddress((void**)&wt,  g_wt);
    __half* woh = nullptr; cudaGetSymbolAddress((void**)&woh, g_woh);

    cvt_f32_f16<<<(M_ * D_) / 1024, 256>>>(X, xh, M_ * D_);
    cvt_f32_f16<<<(D_ * D_) / 1024, 256>>>(Wo, woh, D_ * D_);
    wtrans<<<dim3(2, 32, 48), dim3(32, 8)>>>(Wq, Wk, Wv);

    qkv_mma<<<dim3(H_ / 2, M_ / 128, 3), 256>>>(xh, wt, bq, bk, bv);
    attn_mma<<<dim3(S_ / 128, B_ * H_), 256>>>();
    out_mma<<<dim3(D_ / 128, M_ / 128), 256>>>(wvh, woh, bo, out);
}

// round 6
// speedup vs baseline: 8.5007x; 1.0826x over previous
#include <cuda_runtime.h>
#include <cuda_fp16.h>
#include <math.h>
#include <stdint.h>

#define B_ 4
#define S_ 2048
#define D_ 1024
#define H_ 16
#define HD_ 64
#define M_ (B_*S_)   // 8192

// fp16 scratch
__device__ __half g_qh[(size_t)B_*H_*S_*HD_];
__device__ __half g_kh[(size_t)B_*H_*S_*HD_];
__device__ __half g_vh[(size_t)B_*H_*S_*HD_];
__device__ __half g_xh[(size_t)M_*D_];
__device__ __half g_wvh[(size_t)M_*D_];
__device__ __half g_wt[(size_t)3*H_*HD_*D_];    // [z][h][n=64][k=1024]
__device__ __half g_woh[(size_t)D_*D_];         // [n][k]

// ---------------------------------------------------------------------------
__device__ __forceinline__ uint32_t smem_u32(const void* p) {
    uint32_t a;
    asm("{ .reg .u64 t; cvta.to.shared.u64 t, %1; cvt.u32.u64 %0, t; }" : "=r"(a) : "l"(p));
    return a;
}
__device__ __forceinline__ void cpa16(uint32_t dst, const void* src) {
    asm volatile("cp.async.cg.shared.global [%0], [%1], 16;" :: "r"(dst), "l"(src));
}
__device__ __forceinline__ void cpa_commit() {
    asm volatile("cp.async.commit_group;" ::: "memory");
}
__device__ __forceinline__ float ex2(float x) {
    float r; asm("ex2.approx.ftz.f32 %0, %1;" : "=f"(r) : "f"(x)); return r;
}
__device__ __forceinline__ void mma16816(float c[4], const uint32_t a[4], const uint32_t b[2]) {
    asm volatile("mma.sync.aligned.m16n8k16.row.col.f32.f16.f16.f32 "
                 "{%0,%1,%2,%3}, {%4,%5,%6,%7}, {%8,%9}, {%0,%1,%2,%3};"
                 : "+f"(c[0]), "+f"(c[1]), "+f"(c[2]), "+f"(c[3])
                 : "r"(a[0]), "r"(a[1]), "r"(a[2]), "r"(a[3]), "r"(b[0]), "r"(b[1]));
}

// =================== GEMM: BK=64, 3-stage ring, 1 sync/iter =================
#define RS2 144
#define TILE2 (128 * RS2)          // 18432 B (one 128x64h matrix)
#define STAGE2 (2 * TILE2)         // 36864 B (A+B)
#define GSMEM (3 * STAGE2)         // 110592 B
#define NKT2 16                    // 1024 / 64

__device__ __forceinline__ void load_stage(uint32_t sbase,
                                           const __half* __restrict__ A,
                                           const __half* __restrict__ Bg,
                                           int kt, int tid) {
    const uint32_t sA = sbase, sB = sbase + TILE2;
    #pragma unroll
    for (int i = 0; i < 4; ++i) {
        int idx = tid + i * 256;           // 0..1023
        int row = idx >> 3, c = idx & 7;
        const size_t go = (size_t)row * D_ + kt * 64 + c * 8;
        cpa16(sA + row * RS2 + c * 16, A + go);
        cpa16(sB + row * RS2 + c * 16, Bg + go);
    }
}

__device__ __forceinline__ void stage_compute(uint32_t sA, uint32_t sB,
                                              int warp_m, int warp_n, int lane,
                                              float c[4][4][4]) {
    #pragma unroll
    for (int ks = 0; ks < 4; ++ks) {
        uint32_t a[4][4];
        #pragma unroll
        for (int i = 0; i < 4; ++i) {
            int row = warp_m * 64 + i * 16 + (lane & 15);
            uint32_t addr = sA + row * RS2 + (ks * 16 + (lane >> 4) * 8) * 2;
            asm volatile("ldmatrix.sync.aligned.m8n8.x4.shared.b16 {%0,%1,%2,%3}, [%4];"
                         : "=r"(a[i][0]), "=r"(a[i][1]), "=r"(a[i][2]), "=r"(a[i][3])
                         : "r"(addr));
        }
        uint32_t b[4][2];
        #pragma unroll
        for (int jj = 0; jj < 2; ++jj) {
            int g = lane >> 3, lr = lane & 7;
            int n = warp_n * 32 + jj * 16 + (g >> 1) * 8 + lr;
            uint32_t addr = sB + n * RS2 + (ks * 16 + (g & 1) * 8) * 2;
            uint32_t r0, r1, r2, r3;
            asm volatile("ldmatrix.sync.aligned.m8n8.x4.shared.b16 {%0,%1,%2,%3}, [%4];"
                         : "=r"(r0), "=r"(r1), "=r"(r2), "=r"(r3) : "r"(addr));
            b[jj * 2][0] = r0; b[jj * 2][1] = r1;
            b[jj * 2 + 1][0] = r2; b[jj * 2 + 1][1] = r3;
        }
        #pragma unroll
        for (int i = 0; i < 4; ++i)
            #pragma unroll
            for (int j = 0; j < 4; ++j)
                mma16816(c[i][j], a[i], b[j]);
    }
}

__device__ __forceinline__ void gemm_main(uint32_t s, const __half* __restrict__ A,
                                          const __half* __restrict__ Bg,
                                          int tid, int warp_m, int warp_n, int lane,
                                          float c[4][4][4]) {
    load_stage(s + 0 * STAGE2, A, Bg, 0, tid); cpa_commit();
    load_stage(s + 1 * STAGE2, A, Bg, 1, tid); cpa_commit();

    #pragma unroll 1
    for (int kt = 0; kt < NKT2; ++kt) {
        if (kt < NKT2 - 1) asm volatile("cp.async.wait_group 1;" ::: "memory");
        else               asm volatile("cp.async.wait_group 0;" ::: "memory");
        __syncthreads();
        if (kt + 2 < NKT2) {
            load_stage(s + ((kt + 2) % 3) * STAGE2, A, Bg, kt + 2, tid);
            cpa_commit();
        }
        const uint32_t sb = s + (kt % 3) * STAGE2;
        stage_compute(sb, sb + TILE2, warp_m, warp_n, lane, c);
    }
}

// ---------------------------------------------------------------------------
// QKV projection -> fp16 Q/K/V
// ---------------------------------------------------------------------------
__global__ __launch_bounds__(256) void qkv_mma(
    const __half* __restrict__ Xh, const __half* __restrict__ Wt,
    const float* __restrict__ bq, const float* __restrict__ bk,
    const float* __restrict__ bv) {
    extern __shared__ __align__(16) char sm[];
    const uint32_t s = smem_u32(sm);
    const int tid = threadIdx.x, lane = tid & 31, wid = tid >> 5;
    const int warp_m = wid & 1, warp_n = wid >> 1;
    const int z = blockIdx.z, h0 = blockIdx.x * 2, m0 = blockIdx.y * 128;

    const __half* A  = Xh + (size_t)m0 * D_;
    const __half* Bg = Wt + ((size_t)(z * H_ + h0) * HD_) * D_;
    const float* bias = (z == 0) ? bq : (z == 1) ? bk : bv;
    __half* out       = (z == 0) ? g_qh : (z == 1) ? g_kh : g_vh;

    float c[4][4][4] = {};
    gemm_main(s, A, Bg, tid, warp_m, warp_n, lane, c);

    #pragma unroll
    for (int i = 0; i < 4; ++i) {
        #pragma unroll
        for (int j = 0; j < 4; ++j) {
            const int n = warp_n * 32 + j * 8 + (lane & 3) * 2;
            const int head = h0 + (n >> 6), e = n & 63;
            const float b0 = bias[head * HD_ + e], b1 = bias[head * HD_ + e + 1];
            #pragma unroll
            for (int half_ = 0; half_ < 2; ++half_) {
                const int m = m0 + warp_m * 64 + i * 16 + (lane >> 2) + half_ * 8;
                const int bb = m >> 11, sI = m & 2047;
                __half2 hv = __floats2half2_rn(c[i][j][half_ * 2 + 0] + b0,
                                               c[i][j][half_ * 2 + 1] + b1);
                *(__half2*)(out + (((size_t)(bb * H_ + head) * S_ + sI) * HD_ + e)) = hv;
            }
        }
    }
}

// ---------------------------------------------------------------------------
// Output projection: C = WVh * Woh^T + bo
// ---------------------------------------------------------------------------
__global__ __launch_bounds__(256) void out_mma(
    const __half* __restrict__ WVh, const __half* __restrict__ Woh,
    const float* __restrict__ bo, float* __restrict__ outp) {
    extern __shared__ __align__(16) char sm[];
    const uint32_t s = smem_u32(sm);
    const int tid = threadIdx.x, lane = tid & 31, wid = tid >> 5;
    const int warp_m = wid & 1, warp_n = wid >> 1;
    const int n0 = blockIdx.x * 128, m0 = blockIdx.y * 128;

    const __half* A  = WVh + (size_t)m0 * D_;
    const __half* Bg = Woh + (size_t)n0 * D_;

    float c[4][4][4] = {};
    gemm_main(s, A, Bg, tid, warp_m, warp_n, lane, c);

    #pragma unroll
    for (int i = 0; i < 4; ++i) {
        #pragma unroll
        for (int j = 0; j < 4; ++j) {
            const int n = n0 + warp_n * 32 + j * 8 + (lane & 3) * 2;
            const float b0 = bo[n], b1 = bo[n + 1];
            #pragma unroll
            for (int half_ = 0; half_ < 2; ++half_) {
                const int m = m0 + warp_m * 64 + i * 16 + (lane >> 2) + half_ * 8;
                float2 v;
                v.x = c[i][j][half_ * 2 + 0] + b0;
                v.y = c[i][j][half_ * 2 + 1] + b1;
                *(float2*)(outp + (size_t)m * D_ + n) = v;
            }
        }
    }
}

// =================== attention: 3-stage ring, 1 sync/iter ===================
#define ARS 144
#define ATILE (64 * ARS)           // 9216 B
#define ASTG (2 * ATILE)           // 18432 B (K+V)
#define ASMEM (3 * ASTG)           // 55296 B

__global__ __launch_bounds__(256) void attn_mma() {
    extern __shared__ __align__(16) char sm[];
    const uint32_t s = smem_u32(sm);
    const int tid = threadIdx.x, lane = tid & 31, w = tid >> 5;
    const int bh = blockIdx.y, q0 = blockIdx.x * 128;

    const __half* __restrict__ Qb = g_qh + (size_t)bh * S_ * HD_;
    const __half* __restrict__ Kb = g_kh + (size_t)bh * S_ * HD_;
    const __half* __restrict__ Vb = g_vh + (size_t)bh * S_ * HD_;

    const int r0 = q0 + w * 16 + (lane >> 2);
    const int cq = lane & 3;
    uint32_t qf[4][4];
    {
        const __half2* Qr0 = (const __half2*)(Qb + (size_t)r0 * HD_);
        const __half2* Qr1 = (const __half2*)(Qb + (size_t)(r0 + 8) * HD_);
        #pragma unroll
        for (int t = 0; t < 4; ++t) {
            qf[t][0] = *(const uint32_t*)&Qr0[t * 8 + cq];
            qf[t][1] = *(const uint32_t*)&Qr1[t * 8 + cq];
            qf[t][2] = *(const uint32_t*)&Qr0[t * 8 + 4 + cq];
            qf[t][3] = *(const uint32_t*)&Qr1[t * 8 + 4 + cq];
        }
    }

    float o[8][4];
    #pragma unroll
    for (int j = 0; j < 8; ++j)
        #pragma unroll
        for (int x = 0; x < 4; ++x) o[j][x] = 0.f;
    float m0 = -INFINITY, m1 = -INFINITY, l0 = 0.f, l1 = 0.f;

    const int NT = (q0 + 128) / 64;
    const float SC = 0.18033688f;    // 0.125 * log2(e)

    auto load_tile = [&](int kt, int stg) {
        const uint32_t base = s + stg * ASTG;
        #pragma unroll
        for (int i = 0; i < 2; ++i) {
            int idx = tid + i * 256;
            int row = idx >> 3, c = idx & 7;
            const size_t go = (size_t)(kt * 64 + row) * HD_ + c * 8;
            cpa16(base + row * ARS + c * 16, Kb + go);
            cpa16(base + ATILE + row * ARS + c * 16, Vb + go);
        }
    };

    load_tile(0, 0); cpa_commit();
    if (NT > 1) { load_tile(1, 1); cpa_commit(); }

    const uint32_t kb_lane = (lane & 7) * ARS + ((lane >> 3) & 1) * 16;
    const uint32_t vb_lane = (lane & 15) * ARS;

    #pragma unroll 1
    for (int kt = 0; kt < NT; ++kt) {
        const int k0 = kt * 64;
        if (kt < NT - 1) asm volatile("cp.async.wait_group 1;" ::: "memory");
        else             asm volatile("cp.async.wait_group 0;" ::: "memory");
        __syncthreads();
        if (kt + 2 < NT) { load_tile(kt + 2, (kt + 2) % 3); cpa_commit(); }

        const uint32_t sK = s + (kt % 3) * ASTG, sV = sK + ATILE;

        // ---- S = Q K^T ----
        float sa[8][4];
        #pragma unroll
        for (int j = 0; j < 8; ++j)
            #pragma unroll
            for (int x = 0; x < 4; ++x) sa[j][x] = 0.f;
        #pragma unroll
        for (int t = 0; t < 4; ++t) {
            #pragma unroll
            for (int j = 0; j < 8; ++j) {
                uint32_t b[2];
                uint32_t addr = sK + kb_lane + j * 8 * ARS + t * 32;
                asm volatile("ldmatrix.sync.aligned.m8n8.x2.shared.b16 {%0,%1}, [%2];"
                             : "=r"(b[0]), "=r"(b[1]) : "r"(addr));
                mma16816(sa[j], qf[t], b);
            }
        }

        // ---- mask + online softmax ----
        const bool needmask = (k0 + 63 > r0);
        float tm0 = -INFINITY, tm1 = -INFINITY;
        #pragma unroll
        for (int j = 0; j < 8; ++j) {
            float v0 = sa[j][0] * SC, v1 = sa[j][1] * SC;
            float v2 = sa[j][2] * SC, v3 = sa[j][3] * SC;
            if (needmask) {
                const int col = k0 + j * 8 + (lane & 3) * 2;
                if (col > r0)         v0 = -INFINITY;
                if (col + 1 > r0)     v1 = -INFINITY;
                if (col > r0 + 8)     v2 = -INFINITY;
                if (col + 1 > r0 + 8) v3 = -INFINITY;
            }
            sa[j][0] = v0; sa[j][1] = v1; sa[j][2] = v2; sa[j][3] = v3;
            tm0 = fmaxf(tm0, fmaxf(v0, v1));
            tm1 = fmaxf(tm1, fmaxf(v2, v3));
        }
        tm0 = fmaxf(tm0, __shfl_xor_sync(0xffffffffu, tm0, 1));
        tm0 = fmaxf(tm0, __shfl_xor_sync(0xffffffffu, tm0, 2));
        tm1 = fmaxf(tm1, __shfl_xor_sync(0xffffffffu, tm1, 1));
        tm1 = fmaxf(tm1, __shfl_xor_sync(0xffffffffu, tm1, 2));

        const float mn0 = fmaxf(m0, tm0), mn1 = fmaxf(m1, tm1);
        const float c0 = ex2(m0 - mn0), c1 = ex2(m1 - mn1);
        m0 = mn0; m1 = mn1;

        float ts0 = 0.f, ts1 = 0.f;
        uint32_t pa[4][4];
        #pragma unroll
        for (int j = 0; j < 8; ++j) {
            const float p0 = ex2(sa[j][0] - mn0), p1 = ex2(sa[j][1] - mn0);
            const float p2 = ex2(sa[j][2] - mn1), p3 = ex2(sa[j][3] - mn1);
            ts0 += p0 + p1; ts1 += p2 + p3;
            const __half2 h01 = __floats2half2_rn(p0, p1);
            const __half2 h23 = __floats2half2_rn(p2, p3);
            const int t = j >> 1;
            if ((j & 1) == 0) {
                pa[t][0] = *(const uint32_t*)&h01;
                pa[t][1] = *(const uint32_t*)&h23;
            } else {
                pa[t][2] = *(const uint32_t*)&h01;
                pa[t][3] = *(const uint32_t*)&h23;
            }
        }
        ts0 += __shfl_xor_sync(0xffffffffu, ts0, 1);
        ts0 += __shfl_xor_sync(0xffffffffu, ts0, 2);
        ts1 += __shfl_xor_sync(0xffffffffu, ts1, 1);
        ts1 += __shfl_xor_sync(0xffffffffu, ts1, 2);
        l0 = l0 * c0 + ts0;
        l1 = l1 * c1 + ts1;

        #pragma unroll
        for (int j = 0; j < 8; ++j) {
            o[j][0] *= c0; o[j][1] *= c0;
            o[j][2] *= c1; o[j][3] *= c1;
        }

        // ---- O += P V ----
        #pragma unroll
        for (int t = 0; t < 4; ++t) {
            #pragma unroll
            for (int j = 0; j < 8; ++j) {
                uint32_t b[2];
                uint32_t addr = sV + vb_lane + t * 16 * ARS + j * 16;
                asm volatile("ldmatrix.sync.aligned.m8n8.x2.trans.shared.b16 {%0,%1}, [%2];"
                             : "=r"(b[0]), "=r"(b[1]) : "r"(addr));
                mma16816(o[j], pa[t], b);
            }
        }
    }

    // ---- epilogue ----
    const float i0 = 1.f / l0, i1 = 1.f / l1;
    const int b = bh >> 4, h = bh & 15;
    __half* out0 = g_wvh + ((size_t)(b * S_) + r0) * D_ + h * HD_ + (lane & 3) * 2;
    __half* out1 = g_wvh + ((size_t)(b * S_) + r0 + 8) * D_ + h * HD_ + (lane & 3) * 2;
    #pragma unroll
    for (int j = 0; j < 8; ++j) {
        *(__half2*)(out0 + j * 8) = __floats2half2_rn(o[j][0] * i0, o[j][1] * i0);
        *(__half2*)(out1 + j * 8) = __floats2half2_rn(o[j][2] * i1, o[j][3] * i1);
    }
}

// ---------------------------------------------------------------------------
// converts + weight transpose
// ---------------------------------------------------------------------------
__global__ void cvt_f32_f16(const float* __restrict__ in, __half* __restrict__ out, int n) {
    int i = (blockIdx.x * blockDim.x + threadIdx.x) * 4;
    if (i < n) {
        float4 v = *(const float4*)(in + i);
        __half2* o = (__half2*)(out + i);
        o[0] = __floats2half2_rn(v.x, v.y);
        o[1] = __floats2half2_rn(v.z, v.w);
    }
}

__global__ void wtrans(const float* __restrict__ Wq, const float* __restrict__ Wk,
                       const float* __restrict__ Wv) {
    __shared__ float t[32][33];
    const int zh = blockIdx.z, z = zh >> 4, h = zh & 15;
    const float* W = ((z == 0) ? Wq : (z == 1) ? Wk : Wv) + (size_t)h * D_ * HD_;
    __half* out = g_wt + (size_t)zh * HD_ * D_;
    const int n0 = blockIdx.x * 32, k0 = blockIdx.y * 32;
    const int tx = threadIdx.x, ty = threadIdx.y;
    #pragma unroll
    for (int i = 0; i < 32; i += 8)
        t[ty + i][tx] = W[(size_t)(k0 + ty + i) * HD_ + n0 + tx];
    __syncthreads();
    #pragma unroll
    for (int i = 0; i < 32; i += 8)
        out[(size_t)(n0 + ty + i) * D_ + k0 + tx] = __float2half_rn(t[tx][ty + i]);
}

// ---------------------------------------------------------------------------
extern "C" void kernel_launch(void* const* d_in, const int* in_sizes, int n_in,
                              void* d_out, int out_size) {
    const float* X  = (const float*)d_in[0];
    const float* Wq = (const float*)d_in[1];
    const float* bq = (const float*)d_in[2];
    const float* Wk = (const float*)d_in[3];
    const float* bk = (const float*)d_in[4];
    const float* Wv = (const float*)d_in[5];
    const float* bv = (const float*)d_in[6];
    const float* Wo = (const float*)d_in[7];
    const float* bo = (const float*)d_in[8];
    float* out = (float*)d_out;

    cudaFuncSetAttribute(qkv_mma, cudaFuncAttributeMaxDynamicSharedMemorySize, GSMEM);
    cudaFuncSetAttribute(out_mma, cudaFuncAttributeMaxDynamicSharedMemorySize, GSMEM);
    cudaFuncSetAttribute(attn_mma, cudaFuncAttributeMaxDynamicSharedMemorySize, ASMEM);

    __half* xh  = nullptr; cudaGetSymbolAddress((void**)&xh,  g_xh);
    __half* wvh = nullptr; cudaGetSymbolAddress((void**)&wvh, g_wvh);
    __half* wt  = nullptr; cudaGetSymbolAddress((void**)&wt,  g_wt);
    __half* woh = nullptr; cudaGetSymbolAddress((void**)&woh, g_woh);

    cvt_f32_f16<<<(M_ * D_) / 1024, 256>>>(X, xh, M_ * D_);
    cvt_f32_f16<<<(D_ * D_) / 1024, 256>>>(Wo, woh, D_ * D_);
    wtrans<<<dim3(2, 32, 48), dim3(32, 8)>>>(Wq, Wk, Wv);

    qkv_mma<<<dim3(H_ / 2, M_ / 128, 3), 256, GSMEM>>>(xh, wt, bq, bk, bv);
    attn_mma<<<dim3(S_ / 128, B_ * H_), 256, ASMEM>>>();
    out_mma<<<dim3(D_ / 128, M_ / 128), 256, GSMEM>>>(wvh, woh, bo, out);
}

// round 7
// speedup vs baseline: 8.7535x; 1.0297x over previous
#include <cuda_runtime.h>
#include <cuda_fp16.h>
#include <math.h>
#include <stdint.h>

#define B_ 4
#define S_ 2048
#define D_ 1024
#define H_ 16
#define HD_ 64
#define M_ (B_*S_)   // 8192

// fp16 scratch
__device__ __half g_qh[(size_t)B_*H_*S_*HD_];
__device__ __half g_kh[(size_t)B_*H_*S_*HD_];
__device__ __half g_vh[(size_t)B_*H_*S_*HD_];
__device__ __half g_xh[(size_t)M_*D_];
__device__ __half g_wvh[(size_t)M_*D_];
__device__ __half g_wt[(size_t)3*H_*HD_*D_];    // [z][h][n=64][k=1024]
__device__ __half g_woh[(size_t)D_*D_];         // [n][k]

// ---------------------------------------------------------------------------
__device__ __forceinline__ uint32_t smem_u32(const void* p) {
    uint32_t a;
    asm("{ .reg .u64 t; cvta.to.shared.u64 t, %1; cvt.u32.u64 %0, t; }" : "=r"(a) : "l"(p));
    return a;
}
__device__ __forceinline__ void cpa16(uint32_t dst, const void* src) {
    asm volatile("cp.async.cg.shared.global [%0], [%1], 16;" :: "r"(dst), "l"(src));
}
__device__ __forceinline__ void cpa_commit() {
    asm volatile("cp.async.commit_group;" ::: "memory");
}
__device__ __forceinline__ float ex2(float x) {
    float r; asm("ex2.approx.ftz.f32 %0, %1;" : "=f"(r) : "f"(x)); return r;
}
__device__ __forceinline__ void mma16816(float c[4], const uint32_t a[4], const uint32_t b[2]) {
    asm volatile("mma.sync.aligned.m16n8k16.row.col.f32.f16.f16.f32 "
                 "{%0,%1,%2,%3}, {%4,%5,%6,%7}, {%8,%9}, {%0,%1,%2,%3};"
                 : "+f"(c[0]), "+f"(c[1]), "+f"(c[2]), "+f"(c[3])
                 : "r"(a[0]), "r"(a[1]), "r"(a[2]), "r"(a[3]), "r"(b[0]), "r"(b[1]));
}

// =================== GEMM: BK=64, 3-stage ring, frag pipelining =============
#define RS2 144
#define TILE2 (128 * RS2)          // 18432 B
#define STAGE2 (2 * TILE2)         // 36864 B (A+B)
#define GSMEM (3 * STAGE2)         // 110592 B
#define NKT2 16                    // 1024 / 64

__device__ __forceinline__ void load_stage(uint32_t sbase,
                                           const __half* __restrict__ A,
                                           const __half* __restrict__ Bg,
                                           int kt, int tid) {
    const uint32_t sA = sbase, sB = sbase + TILE2;
    #pragma unroll
    for (int i = 0; i < 4; ++i) {
        int idx = tid + i * 256;
        int row = idx >> 3, c = idx & 7;
        const size_t go = (size_t)row * D_ + kt * 64 + c * 8;
        cpa16(sA + row * RS2 + c * 16, A + go);
        cpa16(sB + row * RS2 + c * 16, Bg + go);
    }
}

// load one ks-step's fragment set (A: 64x16 for this warp, B: 32x16)
__device__ __forceinline__ void load_frags(uint32_t sA, uint32_t sB, int ks,
                                           int warp_m, int warp_n, int lane,
                                           uint32_t a[4][4], uint32_t b[4][2]) {
    #pragma unroll
    for (int i = 0; i < 4; ++i) {
        int row = warp_m * 64 + i * 16 + (lane & 15);
        uint32_t addr = sA + row * RS2 + (ks * 16 + (lane >> 4) * 8) * 2;
        asm volatile("ldmatrix.sync.aligned.m8n8.x4.shared.b16 {%0,%1,%2,%3}, [%4];"
                     : "=r"(a[i][0]), "=r"(a[i][1]), "=r"(a[i][2]), "=r"(a[i][3])
                     : "r"(addr));
    }
    #pragma unroll
    for (int jj = 0; jj < 2; ++jj) {
        int g = lane >> 3, lr = lane & 7;
        int n = warp_n * 32 + jj * 16 + (g >> 1) * 8 + lr;
        uint32_t addr = sB + n * RS2 + (ks * 16 + (g & 1) * 8) * 2;
        uint32_t r0, r1, r2, r3;
        asm volatile("ldmatrix.sync.aligned.m8n8.x4.shared.b16 {%0,%1,%2,%3}, [%4];"
                     : "=r"(r0), "=r"(r1), "=r"(r2), "=r"(r3) : "r"(addr));
        b[jj * 2][0] = r0; b[jj * 2][1] = r1;
        b[jj * 2 + 1][0] = r2; b[jj * 2 + 1][1] = r3;
    }
}

__device__ __forceinline__ void do_mmas(const uint32_t a[4][4], const uint32_t b[4][2],
                                        float c[4][4][4]) {
    #pragma unroll
    for (int i = 0; i < 4; ++i)
        #pragma unroll
        for (int j = 0; j < 4; ++j)
            mma16816(c[i][j], a[i], b[j]);
}

__device__ __forceinline__ void gemm_main(uint32_t s, const __half* __restrict__ A,
                                          const __half* __restrict__ Bg,
                                          int tid, int warp_m, int warp_n, int lane,
                                          float c[4][4][4]) {
    load_stage(s + 0 * STAGE2, A, Bg, 0, tid); cpa_commit();
    load_stage(s + 1 * STAGE2, A, Bg, 1, tid); cpa_commit();

    uint32_t af[2][4][4], bf[2][4][2];

    #pragma unroll 1
    for (int kt = 0; kt < NKT2; ++kt) {
        if (kt < NKT2 - 1) asm volatile("cp.async.wait_group 1;" ::: "memory");
        else               asm volatile("cp.async.wait_group 0;" ::: "memory");
        __syncthreads();
        if (kt + 2 < NKT2) {
            load_stage(s + ((kt + 2) % 3) * STAGE2, A, Bg, kt + 2, tid);
            cpa_commit();
        }
        const uint32_t sA = s + (kt % 3) * STAGE2, sB = sA + TILE2;

        // software-pipelined fragment loop: prefetch ks+1 before MMAs of ks
        load_frags(sA, sB, 0, warp_m, warp_n, lane, af[0], bf[0]);
        #pragma unroll
        for (int ks = 0; ks < 4; ++ks) {
            if (ks < 3)
                load_frags(sA, sB, ks + 1, warp_m, warp_n, lane,
                           af[(ks + 1) & 1], bf[(ks + 1) & 1]);
            do_mmas(af[ks & 1], bf[ks & 1], c);
        }
    }
}

// ---------------------------------------------------------------------------
// QKV projection -> fp16 Q/K/V
// ---------------------------------------------------------------------------
__global__ __launch_bounds__(256, 2) void qkv_mma(
    const __half* __restrict__ Xh, const __half* __restrict__ Wt,
    const float* __restrict__ bq, const float* __restrict__ bk,
    const float* __restrict__ bv) {
    extern __shared__ __align__(16) char sm[];
    const uint32_t s = smem_u32(sm);
    const int tid = threadIdx.x, lane = tid & 31, wid = tid >> 5;
    const int warp_m = wid & 1, warp_n = wid >> 1;
    const int z = blockIdx.z, h0 = blockIdx.x * 2, m0 = blockIdx.y * 128;

    const __half* A  = Xh + (size_t)m0 * D_;
    const __half* Bg = Wt + ((size_t)(z * H_ + h0) * HD_) * D_;
    const float* bias = (z == 0) ? bq : (z == 1) ? bk : bv;
    __half* out       = (z == 0) ? g_qh : (z == 1) ? g_kh : g_vh;

    float c[4][4][4] = {};
    gemm_main(s, A, Bg, tid, warp_m, warp_n, lane, c);

    #pragma unroll
    for (int i = 0; i < 4; ++i) {
        #pragma unroll
        for (int j = 0; j < 4; ++j) {
            const int n = warp_n * 32 + j * 8 + (lane & 3) * 2;
            const int head = h0 + (n >> 6), e = n & 63;
            const float b0 = bias[head * HD_ + e], b1 = bias[head * HD_ + e + 1];
            #pragma unroll
            for (int half_ = 0; half_ < 2; ++half_) {
                const int m = m0 + warp_m * 64 + i * 16 + (lane >> 2) + half_ * 8;
                const int bb = m >> 11, sI = m & 2047;
                __half2 hv = __floats2half2_rn(c[i][j][half_ * 2 + 0] + b0,
                                               c[i][j][half_ * 2 + 1] + b1);
                *(__half2*)(out + (((size_t)(bb * H_ + head) * S_ + sI) * HD_ + e)) = hv;
            }
        }
    }
}

// ---------------------------------------------------------------------------
// Output projection: C = WVh * Woh^T + bo
// ---------------------------------------------------------------------------
__global__ __launch_bounds__(256, 2) void out_mma(
    const __half* __restrict__ WVh, const __half* __restrict__ Woh,
    const float* __restrict__ bo, float* __restrict__ outp) {
    extern __shared__ __align__(16) char sm[];
    const uint32_t s = smem_u32(sm);
    const int tid = threadIdx.x, lane = tid & 31, wid = tid >> 5;
    const int warp_m = wid & 1, warp_n = wid >> 1;
    const int n0 = blockIdx.x * 128, m0 = blockIdx.y * 128;

    const __half* A  = WVh + (size_t)m0 * D_;
    const __half* Bg = Woh + (size_t)n0 * D_;

    float c[4][4][4] = {};
    gemm_main(s, A, Bg, tid, warp_m, warp_n, lane, c);

    #pragma unroll
    for (int i = 0; i < 4; ++i) {
        #pragma unroll
        for (int j = 0; j < 4; ++j) {
            const int n = n0 + warp_n * 32 + j * 8 + (lane & 3) * 2;
            const float b0 = bo[n], b1 = bo[n + 1];
            #pragma unroll
            for (int half_ = 0; half_ < 2; ++half_) {
                const int m = m0 + warp_m * 64 + i * 16 + (lane >> 2) + half_ * 8;
                float2 v;
                v.x = c[i][j][half_ * 2 + 0] + b0;
                v.y = c[i][j][half_ * 2 + 1] + b1;
                *(float2*)(outp + (size_t)m * D_ + n) = v;
            }
        }
    }
}

// =================== attention (unchanged from R6) ==========================
#define ARS 144
#define ATILE (64 * ARS)
#define ASTG (2 * ATILE)
#define ASMEM (3 * ASTG)           // 55296 B

__global__ __launch_bounds__(256) void attn_mma() {
    extern __shared__ __align__(16) char sm[];
    const uint32_t s = smem_u32(sm);
    const int tid = threadIdx.x, lane = tid & 31, w = tid >> 5;
    const int bh = blockIdx.y, q0 = blockIdx.x * 128;

    const __half* __restrict__ Qb = g_qh + (size_t)bh * S_ * HD_;
    const __half* __restrict__ Kb = g_kh + (size_t)bh * S_ * HD_;
    const __half* __restrict__ Vb = g_vh + (size_t)bh * S_ * HD_;

    const int r0 = q0 + w * 16 + (lane >> 2);
    const int cq = lane & 3;
    uint32_t qf[4][4];
    {
        const __half2* Qr0 = (const __half2*)(Qb + (size_t)r0 * HD_);
        const __half2* Qr1 = (const __half2*)(Qb + (size_t)(r0 + 8) * HD_);
        #pragma unroll
        for (int t = 0; t < 4; ++t) {
            qf[t][0] = *(const uint32_t*)&Qr0[t * 8 + cq];
            qf[t][1] = *(const uint32_t*)&Qr1[t * 8 + cq];
            qf[t][2] = *(const uint32_t*)&Qr0[t * 8 + 4 + cq];
            qf[t][3] = *(const uint32_t*)&Qr1[t * 8 + 4 + cq];
        }
    }

    float o[8][4];
    #pragma unroll
    for (int j = 0; j < 8; ++j)
        #pragma unroll
        for (int x = 0; x < 4; ++x) o[j][x] = 0.f;
    float m0 = -INFINITY, m1 = -INFINITY, l0 = 0.f, l1 = 0.f;

    const int NT = (q0 + 128) / 64;
    const float SC = 0.18033688f;

    auto load_tile = [&](int kt, int stg) {
        const uint32_t base = s + stg * ASTG;
        #pragma unroll
        for (int i = 0; i < 2; ++i) {
            int idx = tid + i * 256;
            int row = idx >> 3, c = idx & 7;
            const size_t go = (size_t)(kt * 64 + row) * HD_ + c * 8;
            cpa16(base + row * ARS + c * 16, Kb + go);
            cpa16(base + ATILE + row * ARS + c * 16, Vb + go);
        }
    };

    load_tile(0, 0); cpa_commit();
    if (NT > 1) { load_tile(1, 1); cpa_commit(); }

    const uint32_t kb_lane = (lane & 7) * ARS + ((lane >> 3) & 1) * 16;
    const uint32_t vb_lane = (lane & 15) * ARS;

    #pragma unroll 1
    for (int kt = 0; kt < NT; ++kt) {
        const int k0 = kt * 64;
        if (kt < NT - 1) asm volatile("cp.async.wait_group 1;" ::: "memory");
        else             asm volatile("cp.async.wait_group 0;" ::: "memory");
        __syncthreads();
        if (kt + 2 < NT) { load_tile(kt + 2, (kt + 2) % 3); cpa_commit(); }

        const uint32_t sK = s + (kt % 3) * ASTG, sV = sK + ATILE;

        float sa[8][4];
        #pragma unroll
        for (int j = 0; j < 8; ++j)
            #pragma unroll
            for (int x = 0; x < 4; ++x) sa[j][x] = 0.f;
        #pragma unroll
        for (int t = 0; t < 4; ++t) {
            #pragma unroll
            for (int j = 0; j < 8; ++j) {
                uint32_t b[2];
                uint32_t addr = sK + kb_lane + j * 8 * ARS + t * 32;
                asm volatile("ldmatrix.sync.aligned.m8n8.x2.shared.b16 {%0,%1}, [%2];"
                             : "=r"(b[0]), "=r"(b[1]) : "r"(addr));
                mma16816(sa[j], qf[t], b);
            }
        }

        const bool needmask = (k0 + 63 > r0);
        float tm0 = -INFINITY, tm1 = -INFINITY;
        #pragma unroll
        for (int j = 0; j < 8; ++j) {
            float v0 = sa[j][0] * SC, v1 = sa[j][1] * SC;
            float v2 = sa[j][2] * SC, v3 = sa[j][3] * SC;
            if (needmask) {
                const int col = k0 + j * 8 + (lane & 3) * 2;
                if (col > r0)         v0 = -INFINITY;
                if (col + 1 > r0)     v1 = -INFINITY;
                if (col > r0 + 8)     v2 = -INFINITY;
                if (col + 1 > r0 + 8) v3 = -INFINITY;
            }
            sa[j][0] = v0; sa[j][1] = v1; sa[j][2] = v2; sa[j][3] = v3;
            tm0 = fmaxf(tm0, fmaxf(v0, v1));
            tm1 = fmaxf(tm1, fmaxf(v2, v3));
        }
        tm0 = fmaxf(tm0, __shfl_xor_sync(0xffffffffu, tm0, 1));
        tm0 = fmaxf(tm0, __shfl_xor_sync(0xffffffffu, tm0, 2));
        tm1 = fmaxf(tm1, __shfl_xor_sync(0xffffffffu, tm1, 1));
        tm1 = fmaxf(tm1, __shfl_xor_sync(0xffffffffu, tm1, 2));

        const float mn0 = fmaxf(m0, tm0), mn1 = fmaxf(m1, tm1);
        const float c0 = ex2(m0 - mn0), c1 = ex2(m1 - mn1);
        m0 = mn0; m1 = mn1;

        float ts0 = 0.f, ts1 = 0.f;
        uint32_t pa[4][4];
        #pragma unroll
        for (int j = 0; j < 8; ++j) {
            const float p0 = ex2(sa[j][0] - mn0), p1 = ex2(sa[j][1] - mn0);
            const float p2 = ex2(sa[j][2] - mn1), p3 = ex2(sa[j][3] - mn1);
            ts0 += p0 + p1; ts1 += p2 + p3;
            const __half2 h01 = __floats2half2_rn(p0, p1);
            const __half2 h23 = __floats2half2_rn(p2, p3);
            const int t = j >> 1;
            if ((j & 1) == 0) {
                pa[t][0] = *(const uint32_t*)&h01;
                pa[t][1] = *(const uint32_t*)&h23;
            } else {
                pa[t][2] = *(const uint32_t*)&h01;
                pa[t][3] = *(const uint32_t*)&h23;
            }
        }
        ts0 += __shfl_xor_sync(0xffffffffu, ts0, 1);
        ts0 += __shfl_xor_sync(0xffffffffu, ts0, 2);
        ts1 += __shfl_xor_sync(0xffffffffu, ts1, 1);
        ts1 += __shfl_xor_sync(0xffffffffu, ts1, 2);
        l0 = l0 * c0 + ts0;
        l1 = l1 * c1 + ts1;

        #pragma unroll
        for (int j = 0; j < 8; ++j) {
            o[j][0] *= c0; o[j][1] *= c0;
            o[j][2] *= c1; o[j][3] *= c1;
        }

        #pragma unroll
        for (int t = 0; t < 4; ++t) {
            #pragma unroll
            for (int j = 0; j < 8; ++j) {
                uint32_t b[2];
                uint32_t addr = sV + vb_lane + t * 16 * ARS + j * 16;
                asm volatile("ldmatrix.sync.aligned.m8n8.x2.trans.shared.b16 {%0,%1}, [%2];"
                             : "=r"(b[0]), "=r"(b[1]) : "r"(addr));
                mma16816(o[j], pa[t], b);
            }
        }
    }

    const float i0 = 1.f / l0, i1 = 1.f / l1;
    const int b = bh >> 4, h = bh & 15;
    __half* out0 = g_wvh + ((size_t)(b * S_) + r0) * D_ + h * HD_ + (lane & 3) * 2;
    __half* out1 = g_wvh + ((size_t)(b * S_) + r0 + 8) * D_ + h * HD_ + (lane & 3) * 2;
    #pragma unroll
    for (int j = 0; j < 8; ++j) {
        *(__half2*)(out0 + j * 8) = __floats2half2_rn(o[j][0] * i0, o[j][1] * i0);
        *(__half2*)(out1 + j * 8) = __floats2half2_rn(o[j][2] * i1, o[j][3] * i1);
    }
}

// ---------------------------------------------------------------------------
// converts + weight transpose
// ---------------------------------------------------------------------------
__global__ void cvt_f32_f16(const float* __restrict__ in, __half* __restrict__ out, int n) {
    int i = (blockIdx.x * blockDim.x + threadIdx.x) * 4;
    if (i < n) {
        float4 v = *(const float4*)(in + i);
        __half2* o = (__half2*)(out + i);
        o[0] = __floats2half2_rn(v.x, v.y);
        o[1] = __floats2half2_rn(v.z, v.w);
    }
}

__global__ void wtrans(const float* __restrict__ Wq, const float* __restrict__ Wk,
                       const float* __restrict__ Wv) {
    __shared__ float t[32][33];
    const int zh = blockIdx.z, z = zh >> 4, h = zh & 15;
    const float* W = ((z == 0) ? Wq : (z == 1) ? Wk : Wv) + (size_t)h * D_ * HD_;
    __half* out = g_wt + (size_t)zh * HD_ * D_;
    const int n0 = blockIdx.x * 32, k0 = blockIdx.y * 32;
    const int tx = threadIdx.x, ty = threadIdx.y;
    #pragma unroll
    for (int i = 0; i < 32; i += 8)
        t[ty + i][tx] = W[(size_t)(k0 + ty + i) * HD_ + n0 + tx];
    __syncthreads();
    #pragma unroll
    for (int i = 0; i < 32; i += 8)
        out[(size_t)(n0 + ty + i) * D_ + k0 + tx] = __float2half_rn(t[tx][ty + i]);
}

// ---------------------------------------------------------------------------
extern "C" void kernel_launch(void* const* d_in, const int* in_sizes, int n_in,
                              void* d_out, int out_size) {
    const float* X  = (const float*)d_in[0];
    const float* Wq = (const float*)d_in[1];
    const float* bq = (const float*)d_in[2];
    const float* Wk = (const float*)d_in[3];
    const float* bk = (const float*)d_in[4];
    const float* Wv = (const float*)d_in[5];
    const float* bv = (const float*)d_in[6];
    const float* Wo = (const float*)d_in[7];
    const float* bo = (const float*)d_in[8];
    float* out = (float*)d_out;

    cudaFuncSetAttribute(qkv_mma, cudaFuncAttributeMaxDynamicSharedMemorySize, GSMEM);
    cudaFuncSetAttribute(out_mma, cudaFuncAttributeMaxDynamicSharedMemorySize, GSMEM);
    cudaFuncSetAttribute(attn_mma, cudaFuncAttributeMaxDynamicSharedMemorySize, ASMEM);

    __half* xh  = nullptr; cudaGetSymbolAddress((void**)&xh,  g_xh);
    __half* wvh = nullptr; cudaGetSymbolAddress((void**)&wvh, g_wvh);
    __half* wt  = nullptr; cudaGetSymbolAddress((void**)&wt,  g_wt);
    __half* woh = nullptr; cudaGetSymbolAddress((void**)&woh, g_woh);

    cvt_f32_f16<<<(M_ * D_) / 1024, 256>>>(X, xh, M_ * D_);
    cvt_f32_f16<<<(D_ * D_) / 1024, 256>>>(Wo, woh, D_ * D_);
    wtrans<<<dim3(2, 32, 48), dim3(32, 8)>>>(Wq, Wk, Wv);

    qkv_mma<<<dim3(H_ / 2, M_ / 128, 3), 256, GSMEM>>>(xh, wt, bq, bk, bv);
    attn_mma<<<dim3(S_ / 128, B_ * H_), 256, ASMEM>>>();
    out_mma<<<dim3(D_ / 128, M_ / 128), 256, GSMEM>>>(wvh, woh, bo, out);
}